// round 14
// baseline (speedup 1.0000x reference)
#include <cuda_runtime.h>
#include <cuda_fp16.h>
#include <cstdint>

// Problem constants
#define B_SZ 8192
#define I_SZ 1024
#define O_SZ 1024
#define NB   8

// Packed layouts
#define KTA 5120           // g_A row: 1024 silu + 4096 compressed spline halfs
#define KTW 9216           // g_W row: 1024 base + 8192 reordered spline halfs

// GEMM tiling (R11-proven smem shapes; 512 threads, warp tile 32x32)
#define LDH  40            // padded stride (halfs) for 32-wide tiles
#define LDB2 72            // padded stride (halfs) for 64-wide B tiles
#define P1_TILE 10240      // 128*40*2 bytes
#define P1_STAGE 20480
#define P2_AB 10240        // phase2 A_c tile (128 x 32 halfs @ 40)
#define P2_BB 18432        // phase2 B tile  (128 x 64 halfs @ 72)
#define P2_STAGE (P2_AB + P2_BB)          // 28672
#define DYN_SMEM (2 * P2_STAGE)           // 57344 -> 2 CTAs/SM
#define N1 32              // phase1 iterations
#define N2 128             // phase2 iterations

// Scratch (device globals: allocation-free rule)
__device__ __half   g_A[(size_t)B_SZ * KTA];
__device__ __half   g_W[(size_t)O_SZ * KTW];
__device__ uint32_t g_E[(size_t)(B_SZ / 16) * 8 * 512];   // mma.sp metadata, lane-ready

__device__ __forceinline__ uint32_t smem_u32(const void* p) {
    return (uint32_t)__cvta_generic_to_shared(p);
}
__device__ __forceinline__ void cp16(uint32_t dst, const void* src) {
    asm volatile("cp.async.cg.shared.global [%0], [%1], 16;" :: "r"(dst), "l"(src));
}
__device__ __forceinline__ void ldm_x4(uint32_t* r, uint32_t addr) {
    asm volatile("ldmatrix.sync.aligned.m8n8.x4.shared.b16 {%0,%1,%2,%3}, [%4];"
                 : "=r"(r[0]), "=r"(r[1]), "=r"(r[2]), "=r"(r[3]) : "r"(addr));
}
__device__ __forceinline__ void mma_f16(float* d, const uint32_t* a, uint32_t b0, uint32_t b1) {
    asm volatile(
        "mma.sync.aligned.m16n8k16.row.col.f32.f16.f16.f32 "
        "{%0,%1,%2,%3}, {%4,%5,%6,%7}, {%8,%9}, {%0,%1,%2,%3};"
        : "+f"(d[0]), "+f"(d[1]), "+f"(d[2]), "+f"(d[3])
        : "r"(a[0]), "r"(a[1]), "r"(a[2]), "r"(a[3]), "r"(b0), "r"(b1));
}
__device__ __forceinline__ void mma_sp(float* d, const uint32_t* a,
                                       uint32_t b0, uint32_t b1, uint32_t b2, uint32_t b3,
                                       uint32_t e) {
    asm volatile(
        "mma.sp::ordered_metadata.sync.aligned.m16n8k32.row.col.f32.f16.f16.f32 "
        "{%0,%1,%2,%3}, {%4,%5,%6,%7}, {%8,%9,%10,%11}, {%0,%1,%2,%3}, %12, 0x0;"
        : "+f"(d[0]), "+f"(d[1]), "+f"(d[2]), "+f"(d[3])
        : "r"(a[0]), "r"(a[1]), "r"(a[2]), "r"(a[3]),
          "r"(b0), "r"(b1), "r"(b2), "r"(b3), "r"(e));
}

// ---------------------------------------------------------------------------
// Kernel 1 (merged): blocks [0,4096): activations; [4096,8192): weight pack
// ---------------------------------------------------------------------------
__global__ void __launch_bounds__(256) prep_kernel(const float4* __restrict__ x4,
                                                   const float* __restrict__ bw,
                                                   const float* __restrict__ sw) {
    if (blockIdx.x < 4096) {
        int idx = blockIdx.x * 256 + threadIdx.x;     // 1M threads, 8 inputs each
        int b = idx >> 7, iv = idx & 127;

        float4 v0 = x4[idx * 2], v1 = x4[idx * 2 + 1];
        float xs[8] = {v0.x, v0.y, v0.z, v0.w, v1.x, v1.y, v1.z, v1.w};

        __half2 silu[4];
        __half2 ce[8], co[8];
        uint32_t mb[8];
#pragma unroll
        for (int c = 0; c < 8; c++) {
            float x = xs[c];
            float s = x / (1.0f + __expf(-x));
            if (c & 1) silu[c >> 1] = __floats2half2_rn(xs[c - 1] / (1.0f + __expf(-xs[c - 1])), s);
            float xc = fminf(fmaxf(x, -1.0f), 1.0f);
            float vv = fmaf(xc, 2.5f, 5.5f);
            int i = (int)floorf(vv);
            i = max(3, min(8, i));
            float u = vv - (float)i;
            float um = 1.0f - u;
            float w0 = um * um * um * (1.0f / 6.0f);
            float w1 = ((3.0f * u - 6.0f) * u * u + 4.0f) * (1.0f / 6.0f);
            float w2 = (((-3.0f * u + 3.0f) * u + 3.0f) * u + 1.0f) * (1.0f / 6.0f);
            float w3 = u * u * u * (1.0f / 6.0f);
            int r = i - 3;
            int pe0 = (r >= 5) ? 2 : ((r + 1) >> 1);
            int pe1 = pe0 + 1;
            int po0 = r >> 1, po1 = po0 + 1;
            float ev0, ev1, ov0, ov1;
            if (!(r & 1))      { ev0 = w0;   ev1 = w2; ov0 = w1; ov1 = w3; }
            else if (r == 5)   { ev0 = 0.0f; ev1 = w1; ov0 = w0; ov1 = w2; }
            else               { ev0 = w1;   ev1 = w3; ov0 = w0; ov1 = w2; }
            ce[c] = __floats2half2_rn(ev0, ev1);
            co[c] = __floats2half2_rn(ov0, ov1);
            mb[c] = (uint32_t)((pe0 | (pe1 << 2)) | ((po0 | (po1 << 2)) << 4));
        }

        __half* dstr = g_A + (size_t)b * KTA;
        *reinterpret_cast<uint4*>(dstr + iv * 8) = *reinterpret_cast<uint4*>(silu);

        uint4* cdst = reinterpret_cast<uint4*>(dstr + 1024 + iv * 32);
#pragma unroll
        for (int q = 0; q < 4; q++) {
            __half2 t0 = ce[2 * q], t1 = co[2 * q], t2 = ce[2 * q + 1], t3 = co[2 * q + 1];
            uint4 v;
            v.x = *reinterpret_cast<uint32_t*>(&t0);
            v.y = *reinterpret_cast<uint32_t*>(&t1);
            v.z = *reinterpret_cast<uint32_t*>(&t2);
            v.w = *reinterpret_cast<uint32_t*>(&t3);
            cdst[q] = v;
        }

        uint16_t* eh = reinterpret_cast<uint16_t*>(g_E);
        size_t mbase = ((size_t)(b >> 4) * 8 + (b & 7)) * 512;
        int hi = (b >> 3) & 1;
#pragma unroll
        for (int cc = 0; cc < 2; cc++)
#pragma unroll
            for (int h = 0; h < 2; h++) {
                size_t W = mbase + 2 * (size_t)(2 * iv + cc) + h;
                eh[2 * W + hi] = (uint16_t)(mb[4 * cc + 2 * h] | (mb[4 * cc + 2 * h + 1] << 8));
            }
    } else {
        int t = (blockIdx.x - 4096) * 256 + threadIdx.x;
        int o = t >> 10, i = t & 1023;

        __half* dst = g_W + (size_t)o * KTW;
        dst[i] = __float2half_rn(bw[t]);

        const float4* sp = reinterpret_cast<const float4*>(sw + (size_t)t * NB);
        float4 s0 = sp[0], s1 = sp[1];
        __half2 p0 = __floats2half2_rn(s0.x, s0.z);
        __half2 p1 = __floats2half2_rn(s1.x, s1.z);
        __half2 p2 = __floats2half2_rn(s0.y, s0.w);
        __half2 p3 = __floats2half2_rn(s1.y, s1.w);
        uint4 v;
        v.x = *reinterpret_cast<uint32_t*>(&p0);
        v.y = *reinterpret_cast<uint32_t*>(&p1);
        v.z = *reinterpret_cast<uint32_t*>(&p2);
        v.w = *reinterpret_cast<uint32_t*>(&p3);
        *reinterpret_cast<uint4*>(dst + 1024 + i * 8) = v;
    }
}

// ---------------------------------------------------------------------------
// Kernel 2: GEMM. 512 threads, 16 warps in 4x4 grid, warp tile 32x32
// (32 acc regs/thread -> 2 CTAs/SM at 64-reg cap -> 8 warps/SMSP).
// Phase 1: dense base (K=1024). Phase 2: 2:4 sparse spline (R11 smem shapes).
// ---------------------------------------------------------------------------
__global__ void __launch_bounds__(512, 2) gemm_kernel(float* __restrict__ out) {
    extern __shared__ __align__(16) __half smem[];
    const int tid = threadIdx.x;
    const int m0 = blockIdx.y * 128;
    const int n0 = blockIdx.x * 128;
    const uint32_t sbase = smem_u32(smem);

    const int lane = tid & 31, warp = tid >> 5;
    const int wm = (warp >> 2) * 32;     // 4 warps along M
    const int wn = (warp & 3) * 32;      // 4 warps along N
    const int t4 = lane >> 3, r8 = lane & 7;
    const int a_row = (t4 & 1) * 8 + r8;
    const int a_kad = (t4 >> 1) * 8;
    const int b_row = (t4 >> 1) * 8 + r8;
    const int b_kad = (t4 & 1) * 8;

    float acc[2][4][4];
#pragma unroll
    for (int a = 0; a < 2; a++)
#pragma unroll
        for (int b = 0; b < 4; b++)
#pragma unroll
            for (int c = 0; c < 4; c++) acc[a][b][c] = 0.0f;

    // ================= Phase 1: dense base GEMM, K = 1024, BK = 32 =================
    {
        // 512 chunks of 16B per tile; each thread: 1 A chunk + 1 B chunk
        const int row = tid >> 2, c16 = tid & 3;
        const __half* gA = g_A + (size_t)(m0 + row) * KTA + c16 * 8;
        const __half* gB = g_W + (size_t)(n0 + row) * KTW + c16 * 8;
        const uint32_t dA = sbase + (uint32_t)(row * LDH + c16 * 8) * 2;
        const uint32_t dB = dA + P1_TILE;

        cp16(dA, gA); cp16(dB, gB);
        asm volatile("cp.async.commit_group;");
        asm volatile("cp.async.wait_group 0;");
        __syncthreads();

        for (int t = 0; t < N1; t++) {
            const int cur = t & 1;
            if (t + 1 < N1) {
                const uint32_t soff = (uint32_t)((cur ^ 1) * P1_STAGE);
                const int k0 = (t + 1) * 32;
                cp16(dA + soff, gA + k0);
                cp16(dB + soff, gB + k0);
                asm volatile("cp.async.commit_group;");
            }
            const uint32_t sA = sbase + (uint32_t)(cur * P1_STAGE);
            const uint32_t sB = sA + P1_TILE;
#pragma unroll
            for (int ks = 0; ks < 2; ks++) {
                const int kc = ks * 16;
                uint32_t a[2][4], b[2][4];
#pragma unroll
                for (int im = 0; im < 2; im++)
                    ldm_x4(a[im], sA + (uint32_t)(((wm + im * 16 + a_row) * LDH + kc + a_kad) * 2));
#pragma unroll
                for (int pr = 0; pr < 2; pr++)
                    ldm_x4(b[pr], sB + (uint32_t)(((wn + pr * 16 + b_row) * LDH + kc + b_kad) * 2));
#pragma unroll
                for (int im = 0; im < 2; im++)
#pragma unroll
                    for (int jn = 0; jn < 4; jn++)
                        mma_f16(acc[im][jn], a[im], b[jn >> 1][(jn & 1) * 2], b[jn >> 1][(jn & 1) * 2 + 1]);
            }
            asm volatile("cp.async.wait_group 0;");
            __syncthreads();
        }
    }

    // ========== Phase 2: sparse spline GEMM, sparse K = 64 per iter (128 iters) ==========
    {
        // A_c: 512 chunks -> 1 per thread; B: 1024 chunks -> 2 per thread
        const __half* gA2b = g_A + (size_t)(m0 + (tid >> 2)) * KTA + 1024 + (tid & 3) * 8;
        const uint32_t dA2b = sbase + (uint32_t)((tid >> 2) * LDH + (tid & 3) * 8) * 2;
        const __half* gB2b = g_W + (size_t)(n0 + (tid >> 3)) * KTW + 1024 + (tid & 7) * 8;
        const uint32_t dB2b = sbase + (uint32_t)P2_AB + (uint32_t)((tid >> 3) * LDB2 + (tid & 7) * 8) * 2;

        cp16(dA2b, gA2b);
#pragma unroll
        for (int h = 0; h < 2; h++)
            cp16(dB2b + h * (64 * LDB2 * 2), gB2b + (size_t)h * 64 * KTW);
        asm volatile("cp.async.commit_group;");
        asm volatile("cp.async.wait_group 0;");
        __syncthreads();

        const uint32_t* eP0 = g_E + ((size_t)((m0 + wm) >> 4) * 8 + (lane >> 2)) * 512 + (lane & 1);
        const uint32_t* eP1 = g_E + ((size_t)((m0 + wm + 16) >> 4) * 8 + (lane >> 2)) * 512 + (lane & 1);

        for (int it = 0; it < N2; it++) {
            const int cur = it & 1;
            if (it + 1 < N2) {
                const uint32_t soff = (uint32_t)((cur ^ 1) * P2_STAGE);
                const int ka = (it + 1) * 32, kb = (it + 1) * 64;
                cp16(dA2b + soff, gA2b + ka);
#pragma unroll
                for (int h = 0; h < 2; h++)
                    cp16(dB2b + soff + h * (64 * LDB2 * 2), gB2b + kb + (size_t)h * 64 * KTW);
                asm volatile("cp.async.commit_group;");
            }
            const uint32_t sA = sbase + (uint32_t)(cur * P2_STAGE);
            const uint32_t sB = sA + P2_AB;

#pragma unroll
            for (int cc = 0; cc < 2; cc++) {
                const int chunk = it * 2 + cc;
                uint32_t e0 = eP0[2 * chunk];
                uint32_t e1 = eP1[2 * chunk];
                uint32_t aF[2][4];
#pragma unroll
                for (int im = 0; im < 2; im++)
                    ldm_x4(aF[im], sA + (uint32_t)(((wm + im * 16 + a_row) * LDH + cc * 16 + a_kad) * 2));
#pragma unroll
                for (int pr = 0; pr < 2; pr++) {
                    uint32_t bL[4], bH[4];
                    ldm_x4(bL, sB + (uint32_t)(((wn + pr * 16 + b_row) * LDB2 + cc * 32 + b_kad) * 2));
                    ldm_x4(bH, sB + (uint32_t)(((wn + pr * 16 + b_row) * LDB2 + cc * 32 + 16 + b_kad) * 2));
                    mma_sp(acc[0][2 * pr],     aF[0], bL[0], bL[1], bH[0], bH[1], e0);
                    mma_sp(acc[0][2 * pr + 1], aF[0], bL[2], bL[3], bH[2], bH[3], e0);
                    mma_sp(acc[1][2 * pr],     aF[1], bL[0], bL[1], bH[0], bH[1], e1);
                    mma_sp(acc[1][2 * pr + 1], aF[1], bL[2], bL[3], bH[2], bH[3], e1);
                }
            }
            asm volatile("cp.async.wait_group 0;");
            __syncthreads();
        }
    }

    // ================= Epilogue =================
    const int fr = lane >> 2, fc = lane & 3;
#pragma unroll
    for (int im = 0; im < 2; im++) {
        const int mrow = m0 + wm + im * 16 + fr;
        float* orow0 = out + (size_t)mrow * O_SZ;
        float* orow1 = orow0 + (size_t)8 * O_SZ;
#pragma unroll
        for (int jn = 0; jn < 4; jn++) {
            const int nc = n0 + wn + jn * 8 + 2 * fc;
            *reinterpret_cast<float2*>(orow0 + nc) = make_float2(acc[im][jn][0], acc[im][jn][1]);
            *reinterpret_cast<float2*>(orow1 + nc) = make_float2(acc[im][jn][2], acc[im][jn][3]);
        }
    }
}

// ---------------------------------------------------------------------------
extern "C" void kernel_launch(void* const* d_in, const int* in_sizes, int n_in,
                              void* d_out, int out_size) {
    const float* x  = (const float*)d_in[0];
    const float* bw = (const float*)d_in[1];
    const float* sw = (const float*)d_in[2];
    float* out = (float*)d_out;

    prep_kernel<<<8192, 256>>>(reinterpret_cast<const float4*>(x), bw, sw);

    cudaFuncSetAttribute(gemm_kernel, cudaFuncAttributeMaxDynamicSharedMemorySize, DYN_SMEM);
    dim3 grid(O_SZ / 128, B_SZ / 128);   // 8 x 64
    gemm_kernel<<<grid, 512, DYN_SMEM>>>(out);
}

// round 15
// speedup vs baseline: 1.5648x; 1.5648x over previous
#include <cuda_runtime.h>
#include <cuda_fp16.h>
#include <cstdint>

// Problem constants
#define B_SZ 8192
#define I_SZ 1024
#define O_SZ 1024
#define NB   8

// Packed layouts
#define KTA 5120           // g_A row: 1024 silu + 4096 compressed spline halfs
#define KTW 9216           // g_W row: 1024 base + 8192 reordered spline halfs

// GEMM tiling (R11 shapes + 1KB metadata stage)
#define LDH  40            // padded stride (halfs) for 32-wide tiles
#define LDB2 72            // padded stride (halfs) for 64-wide B tiles
#define P1_TILE 10240      // 128*40*2 bytes
#define P1_STAGE 20480
#define P2_AB 10240        // phase2 A_c tile bytes (128 x 32 halfs @ 40)
#define P2_BB 18432        // phase2 B tile bytes  (128 x 64 halfs @ 72)
#define P2_EB 1024         // phase2 metadata bytes (8 groups x 8 slots x 16B)
#define P2_STAGE (P2_AB + P2_BB + P2_EB)  // 29696
#define DYN_SMEM (2 * P2_STAGE)           // 59392 -> 2 CTAs/SM
#define N1 32              // phase1 iterations
#define N2 128             // phase2 iterations

// Scratch (device globals: allocation-free rule)
__device__ __half   g_A[(size_t)B_SZ * KTA];
__device__ __half   g_W[(size_t)O_SZ * KTW];
__device__ uint32_t g_E[(size_t)(B_SZ / 16) * 8 * 512];   // mma.sp metadata, lane-ready

__device__ __forceinline__ uint32_t smem_u32(const void* p) {
    return (uint32_t)__cvta_generic_to_shared(p);
}
__device__ __forceinline__ void cp16(uint32_t dst, const void* src) {
    asm volatile("cp.async.cg.shared.global [%0], [%1], 16;" :: "r"(dst), "l"(src));
}
__device__ __forceinline__ uint32_t lds32(uint32_t addr) {
    uint32_t v;
    asm volatile("ld.shared.b32 %0, [%1];" : "=r"(v) : "r"(addr));
    return v;
}
__device__ __forceinline__ void ldm_x4(uint32_t* r, uint32_t addr) {
    asm volatile("ldmatrix.sync.aligned.m8n8.x4.shared.b16 {%0,%1,%2,%3}, [%4];"
                 : "=r"(r[0]), "=r"(r[1]), "=r"(r[2]), "=r"(r[3]) : "r"(addr));
}
__device__ __forceinline__ void mma_f16(float* d, const uint32_t* a, uint32_t b0, uint32_t b1) {
    asm volatile(
        "mma.sync.aligned.m16n8k16.row.col.f32.f16.f16.f32 "
        "{%0,%1,%2,%3}, {%4,%5,%6,%7}, {%8,%9}, {%0,%1,%2,%3};"
        : "+f"(d[0]), "+f"(d[1]), "+f"(d[2]), "+f"(d[3])
        : "r"(a[0]), "r"(a[1]), "r"(a[2]), "r"(a[3]), "r"(b0), "r"(b1));
}
__device__ __forceinline__ void mma_sp(float* d, const uint32_t* a,
                                       uint32_t b0, uint32_t b1, uint32_t b2, uint32_t b3,
                                       uint32_t e) {
    asm volatile(
        "mma.sp::ordered_metadata.sync.aligned.m16n8k32.row.col.f32.f16.f16.f32 "
        "{%0,%1,%2,%3}, {%4,%5,%6,%7}, {%8,%9,%10,%11}, {%0,%1,%2,%3}, %12, 0x0;"
        : "+f"(d[0]), "+f"(d[1]), "+f"(d[2]), "+f"(d[3])
        : "r"(a[0]), "r"(a[1]), "r"(a[2]), "r"(a[3]),
          "r"(b0), "r"(b1), "r"(b2), "r"(b3), "r"(e));
}

// ---------------------------------------------------------------------------
// Kernel 1 (merged): blocks [0,4096): activations; [4096,8192): weight pack
// ---------------------------------------------------------------------------
__global__ void __launch_bounds__(256) prep_kernel(const float4* __restrict__ x4,
                                                   const float* __restrict__ bw,
                                                   const float* __restrict__ sw) {
    if (blockIdx.x < 4096) {
        int idx = blockIdx.x * 256 + threadIdx.x;     // 1M threads, 8 inputs each
        int b = idx >> 7, iv = idx & 127;

        float4 v0 = x4[idx * 2], v1 = x4[idx * 2 + 1];
        float xs[8] = {v0.x, v0.y, v0.z, v0.w, v1.x, v1.y, v1.z, v1.w};

        __half2 silu[4];
        __half2 ce[8], co[8];
        uint32_t mb[8];
#pragma unroll
        for (int c = 0; c < 8; c++) {
            float x = xs[c];
            float s = x / (1.0f + __expf(-x));
            if (c & 1) silu[c >> 1] = __floats2half2_rn(xs[c - 1] / (1.0f + __expf(-xs[c - 1])), s);
            float xc = fminf(fmaxf(x, -1.0f), 1.0f);
            float vv = fmaf(xc, 2.5f, 5.5f);
            int i = (int)floorf(vv);
            i = max(3, min(8, i));
            float u = vv - (float)i;
            float um = 1.0f - u;
            float w0 = um * um * um * (1.0f / 6.0f);
            float w1 = ((3.0f * u - 6.0f) * u * u + 4.0f) * (1.0f / 6.0f);
            float w2 = (((-3.0f * u + 3.0f) * u + 3.0f) * u + 1.0f) * (1.0f / 6.0f);
            float w3 = u * u * u * (1.0f / 6.0f);
            int r = i - 3;
            int pe0 = (r >= 5) ? 2 : ((r + 1) >> 1);
            int pe1 = pe0 + 1;
            int po0 = r >> 1, po1 = po0 + 1;
            float ev0, ev1, ov0, ov1;
            if (!(r & 1))      { ev0 = w0;   ev1 = w2; ov0 = w1; ov1 = w3; }
            else if (r == 5)   { ev0 = 0.0f; ev1 = w1; ov0 = w0; ov1 = w2; }
            else               { ev0 = w1;   ev1 = w3; ov0 = w0; ov1 = w2; }
            ce[c] = __floats2half2_rn(ev0, ev1);
            co[c] = __floats2half2_rn(ov0, ov1);
            mb[c] = (uint32_t)((pe0 | (pe1 << 2)) | ((po0 | (po1 << 2)) << 4));
        }

        __half* dstr = g_A + (size_t)b * KTA;
        *reinterpret_cast<uint4*>(dstr + iv * 8) = *reinterpret_cast<uint4*>(silu);

        uint4* cdst = reinterpret_cast<uint4*>(dstr + 1024 + iv * 32);
#pragma unroll
        for (int q = 0; q < 4; q++) {
            __half2 t0 = ce[2 * q], t1 = co[2 * q], t2 = ce[2 * q + 1], t3 = co[2 * q + 1];
            uint4 v;
            v.x = *reinterpret_cast<uint32_t*>(&t0);
            v.y = *reinterpret_cast<uint32_t*>(&t1);
            v.z = *reinterpret_cast<uint32_t*>(&t2);
            v.w = *reinterpret_cast<uint32_t*>(&t3);
            cdst[q] = v;
        }

        uint16_t* eh = reinterpret_cast<uint16_t*>(g_E);
        size_t mbase = ((size_t)(b >> 4) * 8 + (b & 7)) * 512;
        int hi = (b >> 3) & 1;
#pragma unroll
        for (int cc = 0; cc < 2; cc++)
#pragma unroll
            for (int h = 0; h < 2; h++) {
                size_t W = mbase + 2 * (size_t)(2 * iv + cc) + h;
                eh[2 * W + hi] = (uint16_t)(mb[4 * cc + 2 * h] | (mb[4 * cc + 2 * h + 1] << 8));
            }
    } else {
        int t = (blockIdx.x - 4096) * 256 + threadIdx.x;
        int o = t >> 10, i = t & 1023;

        __half* dst = g_W + (size_t)o * KTW;
        dst[i] = __float2half_rn(bw[t]);

        const float4* sp = reinterpret_cast<const float4*>(sw + (size_t)t * NB);
        float4 s0 = sp[0], s1 = sp[1];
        __half2 p0 = __floats2half2_rn(s0.x, s0.z);
        __half2 p1 = __floats2half2_rn(s1.x, s1.z);
        __half2 p2 = __floats2half2_rn(s0.y, s0.w);
        __half2 p3 = __floats2half2_rn(s1.y, s1.w);
        uint4 v;
        v.x = *reinterpret_cast<uint32_t*>(&p0);
        v.y = *reinterpret_cast<uint32_t*>(&p1);
        v.z = *reinterpret_cast<uint32_t*>(&p2);
        v.w = *reinterpret_cast<uint32_t*>(&p3);
        *reinterpret_cast<uint4*>(dst + 1024 + i * 8) = v;
    }
}

// ---------------------------------------------------------------------------
// Kernel 2: GEMM (R11 base). Phase 2 metadata staged through smem via the
// cp.async pipeline: inner loop reads e via LDS instead of exposed LDG.
// ---------------------------------------------------------------------------
__global__ void __launch_bounds__(256, 2) gemm_kernel(float* __restrict__ out) {
    extern __shared__ __align__(16) __half smem[];
    const int tid = threadIdx.x;
    const int m0 = blockIdx.y * 128;
    const int n0 = blockIdx.x * 128;
    const uint32_t sbase = smem_u32(smem);

    const int lane = tid & 31, warp = tid >> 5;
    const int wm = (warp >> 1) * 32;
    const int wn = (warp & 1) * 64;
    const int t4 = lane >> 3, r8 = lane & 7;
    const int a_row = (t4 & 1) * 8 + r8;
    const int a_kad = (t4 >> 1) * 8;
    const int b_row = (t4 >> 1) * 8 + r8;
    const int b_kad = (t4 & 1) * 8;

    float acc[2][8][4];
#pragma unroll
    for (int a = 0; a < 2; a++)
#pragma unroll
        for (int b = 0; b < 8; b++)
#pragma unroll
            for (int c = 0; c < 4; c++) acc[a][b][c] = 0.0f;

    // ================= Phase 1: dense base GEMM, K = 1024, BK = 32 =================
    {
        const __half* gA[2]; const __half* gB[2];
        uint32_t dA[2], dB[2];
#pragma unroll
        for (int h = 0; h < 2; h++) {
            int c = tid + h * 256;
            int row = c >> 2, c16 = c & 3;
            gA[h] = g_A + (size_t)(m0 + row) * KTA + c16 * 8;
            gB[h] = g_W + (size_t)(n0 + row) * KTW + c16 * 8;
            dA[h] = sbase + (uint32_t)(row * LDH + c16 * 8) * 2;
            dB[h] = dA[h] + P1_TILE;
        }
#pragma unroll
        for (int h = 0; h < 2; h++) { cp16(dA[h], gA[h]); cp16(dB[h], gB[h]); }
        asm volatile("cp.async.commit_group;");
        asm volatile("cp.async.wait_group 0;");
        __syncthreads();

        for (int t = 0; t < N1; t++) {
            const int cur = t & 1;
            if (t + 1 < N1) {
                const uint32_t soff = (uint32_t)((cur ^ 1) * P1_STAGE);
                const int k0 = (t + 1) * 32;
#pragma unroll
                for (int h = 0; h < 2; h++) { cp16(dA[h] + soff, gA[h] + k0); cp16(dB[h] + soff, gB[h] + k0); }
                asm volatile("cp.async.commit_group;");
            }
            const uint32_t sA = sbase + (uint32_t)(cur * P1_STAGE);
            const uint32_t sB = sA + P1_TILE;
#pragma unroll
            for (int ks = 0; ks < 2; ks++) {
                const int kc = ks * 16;
                uint32_t a[2][4], b[4][4];
#pragma unroll
                for (int im = 0; im < 2; im++)
                    ldm_x4(a[im], sA + (uint32_t)(((wm + im * 16 + a_row) * LDH + kc + a_kad) * 2));
#pragma unroll
                for (int pr = 0; pr < 4; pr++)
                    ldm_x4(b[pr], sB + (uint32_t)(((wn + pr * 16 + b_row) * LDH + kc + b_kad) * 2));
#pragma unroll
                for (int im = 0; im < 2; im++)
#pragma unroll
                    for (int jn = 0; jn < 8; jn++)
                        mma_f16(acc[im][jn], a[im], b[jn >> 1][(jn & 1) * 2], b[jn >> 1][(jn & 1) * 2 + 1]);
            }
            asm volatile("cp.async.wait_group 0;");
            __syncthreads();
        }
    }

    // ================= Phase 2: sparse spline GEMM, sparse K = 8192, 64/iter =================
    {
        const __half* gA2[2]; const __half* gB2[4];
        uint32_t dA2[2], dB2[4];
#pragma unroll
        for (int h = 0; h < 2; h++) {
            int c = tid + h * 256;
            int row = c >> 2, o16 = c & 3;
            gA2[h] = g_A + (size_t)(m0 + row) * KTA + 1024 + o16 * 8;
            dA2[h] = sbase + (uint32_t)(row * LDH + o16 * 8) * 2;
        }
#pragma unroll
        for (int h = 0; h < 4; h++) {
            int c = tid + h * 256;
            int row = c >> 3, o8 = c & 7;
            gB2[h] = g_W + (size_t)(n0 + row) * KTW + 1024 + o8 * 8;
            dB2[h] = sbase + (uint32_t)P2_AB + (uint32_t)(row * LDB2 + o8 * 8) * 2;
        }
        // metadata copy mapping: threads 0..63, one 16B run per (group, slot)
        // src: g_E word ((G0 + (tid>>3))*8 + (tid&7))*512 + 4*it ; dst: EOFF + tid*16
        const uint32_t* gEb = g_E + ((size_t)(m0 >> 4) + (tid >> 3)) * 8 * 512 + (size_t)(tid & 7) * 512;
        const uint32_t dEb = sbase + (uint32_t)(P2_AB + P2_BB) + (uint32_t)tid * 16;
        const bool emover = (tid < 64);

#pragma unroll
        for (int h = 0; h < 2; h++) cp16(dA2[h], gA2[h]);
#pragma unroll
        for (int h = 0; h < 4; h++) cp16(dB2[h], gB2[h]);
        if (emover) cp16(dEb, gEb);
        asm volatile("cp.async.commit_group;");
        asm volatile("cp.async.wait_group 0;");
        __syncthreads();

        // smem metadata read addresses (constant across iterations, per stage)
        const uint32_t eOff = (uint32_t)(P2_AB + P2_BB)
                            + (uint32_t)((wm >> 4) * 128 + (lane >> 2) * 16 + (lane & 1) * 4);

        for (int it = 0; it < N2; it++) {
            const int cur = it & 1;
            if (it + 1 < N2) {
                const uint32_t soff = (uint32_t)((cur ^ 1) * P2_STAGE);
                const int ka = (it + 1) * 32, kb = (it + 1) * 64;
#pragma unroll
                for (int h = 0; h < 2; h++) cp16(dA2[h] + soff, gA2[h] + ka);
#pragma unroll
                for (int h = 0; h < 4; h++) cp16(dB2[h] + soff, gB2[h] + kb);
                if (emover) cp16(dEb + soff, gEb + 4 * (it + 1));
                asm volatile("cp.async.commit_group;");
            }
            const uint32_t sA = sbase + (uint32_t)(cur * P2_STAGE);
            const uint32_t sB = sA + P2_AB;
            const uint32_t sE = sA + eOff;

#pragma unroll
            for (int cc = 0; cc < 2; cc++) {
                uint32_t e0 = lds32(sE + cc * 8);
                uint32_t e1 = lds32(sE + cc * 8 + 128);
                uint32_t aF[2][4];
#pragma unroll
                for (int im = 0; im < 2; im++)
                    ldm_x4(aF[im], sA + (uint32_t)(((wm + im * 16 + a_row) * LDH + cc * 16 + a_kad) * 2));
#pragma unroll
                for (int pr = 0; pr < 4; pr++) {
                    uint32_t bL[4], bH[4];
                    ldm_x4(bL, sB + (uint32_t)(((wn + pr * 16 + b_row) * LDB2 + cc * 32 + b_kad) * 2));
                    ldm_x4(bH, sB + (uint32_t)(((wn + pr * 16 + b_row) * LDB2 + cc * 32 + 16 + b_kad) * 2));
                    mma_sp(acc[0][2 * pr],     aF[0], bL[0], bL[1], bH[0], bH[1], e0);
                    mma_sp(acc[0][2 * pr + 1], aF[0], bL[2], bL[3], bH[2], bH[3], e0);
                    mma_sp(acc[1][2 * pr],     aF[1], bL[0], bL[1], bH[0], bH[1], e1);
                    mma_sp(acc[1][2 * pr + 1], aF[1], bL[2], bL[3], bH[2], bH[3], e1);
                }
            }
            asm volatile("cp.async.wait_group 0;");
            __syncthreads();
        }
    }

    // ================= Epilogue =================
    const int fr = lane >> 2, fc = lane & 3;
#pragma unroll
    for (int im = 0; im < 2; im++) {
        const int mrow = m0 + wm + im * 16 + fr;
        float* orow0 = out + (size_t)mrow * O_SZ;
        float* orow1 = orow0 + (size_t)8 * O_SZ;
#pragma unroll
        for (int jn = 0; jn < 8; jn++) {
            const int nc = n0 + wn + jn * 8 + 2 * fc;
            *reinterpret_cast<float2*>(orow0 + nc) = make_float2(acc[im][jn][0], acc[im][jn][1]);
            *reinterpret_cast<float2*>(orow1 + nc) = make_float2(acc[im][jn][2], acc[im][jn][3]);
        }
    }
}

// ---------------------------------------------------------------------------
extern "C" void kernel_launch(void* const* d_in, const int* in_sizes, int n_in,
                              void* d_out, int out_size) {
    const float* x  = (const float*)d_in[0];
    const float* bw = (const float*)d_in[1];
    const float* sw = (const float*)d_in[2];
    float* out = (float*)d_out;

    prep_kernel<<<8192, 256>>>(reinterpret_cast<const float4*>(x), bw, sw);

    cudaFuncSetAttribute(gemm_kernel, cudaFuncAttributeMaxDynamicSharedMemorySize, DYN_SMEM);
    dim3 grid(O_SZ / 128, B_SZ / 128);   // 8 x 64
    gemm_kernel<<<grid, 256, DYN_SMEM>>>(out);
}